// round 1
// baseline (speedup 1.0000x reference)
#include <cuda_runtime.h>
#include <math.h>

#define BATCH   2
#define S_LEN   2048
#define NHEAD   16
#define DK      64
#define DMODEL  1024
#define MROWS   (BATCH * S_LEN)   // 4096

// ---------------- scratch (device globals: no allocation allowed) ----------------
__device__ float g_q[BATCH * NHEAD * S_LEN * DK];   // (b,h,s,d)
__device__ float g_k[BATCH * NHEAD * S_LEN * DK];
__device__ float g_v[BATCH * NHEAD * S_LEN * DK];
__device__ float g_att[MROWS * DMODEL];             // (b*s, h*dk) row-major
__device__ float g_cos[S_LEN * (DK / 2)];           // [pos][pair]
__device__ float g_sin[S_LEN * (DK / 2)];

// ---------------- RoPE tables (double precision, matches jnp to fp32 ulp) --------
__global__ void rope_table_kernel() {
    int idx = blockIdx.x * blockDim.x + threadIdx.x;    // 2048*32 = 65536
    if (idx >= S_LEN * (DK / 2)) return;
    int pos = idx >> 5;
    int pr  = idx & 31;
    // inv_freq = 10000^(-2*pr/64) = exp(-pr * ln(10000)/32)
    double inv = exp(-(double)pr * 0.28782313662425575);
    double ang = (double)pos * inv;
    g_cos[idx] = (float)cos(ang);
    g_sin[idx] = (float)sin(ang);
}

// ---------------- fused QKV projection GEMM (NT) + RoPE + head scatter -----------
// out[m,n] = sum_k x[m,k] * w[n,k];  m = b*S+s, n = h*64+d
// blockIdx.z: 0 -> Q (rope), 1 -> K (rope), 2 -> V (plain)
__global__ __launch_bounds__(256) void gemm_qkv_kernel(
    const float* __restrict__ x,
    const float* __restrict__ wq, const float* __restrict__ wk,
    const float* __restrict__ wv,
    const int*   __restrict__ positions)
{
    __shared__ __align__(16) float As[16][68];
    __shared__ __align__(16) float Bs[16][68];

    const float* Bw; float* dst; int rope;
    if      (blockIdx.z == 0) { Bw = wq; dst = g_q; rope = 1; }
    else if (blockIdx.z == 1) { Bw = wk; dst = g_k; rope = 1; }
    else                      { Bw = wv; dst = g_v; rope = 0; }

    const int tid = threadIdx.x;
    const int tx = tid & 15, ty = tid >> 4;
    const int m0 = blockIdx.y * 64, n0 = blockIdx.x * 64;
    const int lr = tid >> 2;            // 0..63
    const int lc = (tid & 3) << 2;      // 0,4,8,12

    float acc[4][4] = {};
    const float* Aptr = x  + (size_t)(m0 + lr) * DMODEL + lc;
    const float* Bptr = Bw + (size_t)(n0 + lr) * DMODEL + lc;

    for (int k0 = 0; k0 < DMODEL; k0 += 16) {
        float4 a = *(const float4*)(Aptr + k0);
        float4 b = *(const float4*)(Bptr + k0);
        __syncthreads();
        As[lc + 0][lr] = a.x; As[lc + 1][lr] = a.y;
        As[lc + 2][lr] = a.z; As[lc + 3][lr] = a.w;
        Bs[lc + 0][lr] = b.x; Bs[lc + 1][lr] = b.y;
        Bs[lc + 2][lr] = b.z; Bs[lc + 3][lr] = b.w;
        __syncthreads();
        #pragma unroll
        for (int kk = 0; kk < 16; kk++) {
            float4 a4 = *(const float4*)&As[kk][ty << 2];
            float4 b4 = *(const float4*)&Bs[kk][tx << 2];
            float av[4] = {a4.x, a4.y, a4.z, a4.w};
            float bv[4] = {b4.x, b4.y, b4.z, b4.w};
            #pragma unroll
            for (int i = 0; i < 4; i++)
                #pragma unroll
                for (int j = 0; j < 4; j++)
                    acc[i][j] += av[i] * bv[j];
        }
    }

    const int c0 = n0 + (tx << 2);
    const int h  = c0 >> 6;
    const int d0 = c0 & 63;
    #pragma unroll
    for (int i = 0; i < 4; i++) {
        int r  = m0 + (ty << 2) + i;
        int bb = r >> 11;          // / 2048
        int ss = r & 2047;
        if (rope) {
            int p = positions[ss];
            int pr0 = d0 >> 1;
            #pragma unroll
            for (int jp = 0; jp < 4; jp += 2) {
                int pr = pr0 + (jp >> 1);
                float cs = g_cos[p * 32 + pr];
                float sn = g_sin[p * 32 + pr];
                float x0 = acc[i][jp], x1 = acc[i][jp + 1];
                acc[i][jp]     = x0 * cs - x1 * sn;
                acc[i][jp + 1] = x0 * sn + x1 * cs;
            }
        }
        float4 v4 = make_float4(acc[i][0], acc[i][1], acc[i][2], acc[i][3]);
        *(float4*)(dst + (((size_t)(bb * NHEAD + h) * S_LEN + ss) * DK + d0)) = v4;
    }
}

// ---------------- causal flash attention ----------------------------------------
// grid: (S/64 q-tiles, B*H). 64 threads, 1 query row each. dk=64 in registers.
__global__ __launch_bounds__(64) void attn_kernel() {
    __shared__ __align__(16) float ksh[64 * 64];
    __shared__ __align__(16) float vsh[64 * 64];
    __shared__ float ssh[64 * 33];    // per-thread 32 scores, padded (stride 33)

    const int tid = threadIdx.x;
    const int qt  = blockIdx.x;
    const int bh  = blockIdx.y;
    const int qi  = qt * 64 + tid;

    const float4* Qp = (const float4*)(g_q + ((size_t)bh * S_LEN + qi) * DK);
    float4 q4[16], o4[16];
    #pragma unroll
    for (int i = 0; i < 16; i++) { q4[i] = Qp[i]; o4[i] = make_float4(0.f, 0.f, 0.f, 0.f); }

    float mrun = -1e30f, l = 0.f;

    for (int kt = 0; kt <= qt; kt++) {
        const float4* kb = (const float4*)(g_k + ((size_t)bh * S_LEN + kt * 64) * DK);
        const float4* vb = (const float4*)(g_v + ((size_t)bh * S_LEN + kt * 64) * DK);
        __syncthreads();
        #pragma unroll
        for (int i = 0; i < 16; i++) {
            int f = tid + i * 64;
            ((float4*)ksh)[f] = kb[f];
            ((float4*)vsh)[f] = vb[f];
        }
        __syncthreads();
        const bool diag = (kt == qt);

        #pragma unroll 1
        for (int half = 0; half < 2; half++) {
            const int jbase = half * 32;
            float mt = -1e30f;
            #pragma unroll 1
            for (int jj = 0; jj < 32; jj++) {
                int j = jbase + jj;
                const float4* kr = (const float4*)(ksh + j * 64);
                float4 a = make_float4(0.f, 0.f, 0.f, 0.f);
                #pragma unroll
                for (int i = 0; i < 16; i++) {
                    float4 k4 = kr[i];
                    a.x += q4[i].x * k4.x; a.y += q4[i].y * k4.y;
                    a.z += q4[i].z * k4.z; a.w += q4[i].w * k4.w;
                }
                float s = (a.x + a.y + a.z + a.w) * 0.125f;
                if (diag && j > tid) s = -1e30f;
                ssh[tid * 33 + jj] = s;
                mt = fmaxf(mt, s);
            }
            float mnew = fmaxf(mrun, mt);
            float corr = __expf(mrun - mnew);
            l *= corr;
            #pragma unroll
            for (int i = 0; i < 16; i++) {
                o4[i].x *= corr; o4[i].y *= corr; o4[i].z *= corr; o4[i].w *= corr;
            }
            #pragma unroll 1
            for (int jj = 0; jj < 32; jj++) {
                float p = __expf(ssh[tid * 33 + jj] - mnew);
                l += p;
                const float4* vr = (const float4*)(vsh + (jbase + jj) * 64);
                #pragma unroll
                for (int i = 0; i < 16; i++) {
                    float4 v4 = vr[i];
                    o4[i].x += p * v4.x; o4[i].y += p * v4.y;
                    o4[i].z += p * v4.z; o4[i].w += p * v4.w;
                }
            }
            mrun = mnew;
        }
    }

    const float inv = 1.f / l;
    const int b = bh / NHEAD, h = bh % NHEAD;
    float4* out = (float4*)(g_att + (size_t)(b * S_LEN + qi) * DMODEL + h * DK);
    #pragma unroll
    for (int i = 0; i < 16; i++) {
        float4 v = o4[i];
        v.x *= inv; v.y *= inv; v.z *= inv; v.w *= inv;
        out[i] = v;
    }
}

// ---------------- output projection GEMM (NT): d_out = g_att @ w_o^T ------------
__global__ __launch_bounds__(256) void gemm_out_kernel(
    const float* __restrict__ wo, float* __restrict__ out)
{
    __shared__ __align__(16) float As[16][68];
    __shared__ __align__(16) float Bs[16][68];

    const int tid = threadIdx.x;
    const int tx = tid & 15, ty = tid >> 4;
    const int m0 = blockIdx.y * 64, n0 = blockIdx.x * 64;
    const int lr = tid >> 2;
    const int lc = (tid & 3) << 2;

    float acc[4][4] = {};
    const float* Aptr = g_att + (size_t)(m0 + lr) * DMODEL + lc;
    const float* Bptr = wo    + (size_t)(n0 + lr) * DMODEL + lc;

    for (int k0 = 0; k0 < DMODEL; k0 += 16) {
        float4 a = *(const float4*)(Aptr + k0);
        float4 b = *(const float4*)(Bptr + k0);
        __syncthreads();
        As[lc + 0][lr] = a.x; As[lc + 1][lr] = a.y;
        As[lc + 2][lr] = a.z; As[lc + 3][lr] = a.w;
        Bs[lc + 0][lr] = b.x; Bs[lc + 1][lr] = b.y;
        Bs[lc + 2][lr] = b.z; Bs[lc + 3][lr] = b.w;
        __syncthreads();
        #pragma unroll
        for (int kk = 0; kk < 16; kk++) {
            float4 a4 = *(const float4*)&As[kk][ty << 2];
            float4 b4 = *(const float4*)&Bs[kk][tx << 2];
            float av[4] = {a4.x, a4.y, a4.z, a4.w};
            float bv[4] = {b4.x, b4.y, b4.z, b4.w};
            #pragma unroll
            for (int i = 0; i < 4; i++)
                #pragma unroll
                for (int j = 0; j < 4; j++)
                    acc[i][j] += av[i] * bv[j];
        }
    }

    const int c0 = n0 + (tx << 2);
    #pragma unroll
    for (int i = 0; i < 4; i++) {
        int r = m0 + (ty << 2) + i;
        float4 v4 = make_float4(acc[i][0], acc[i][1], acc[i][2], acc[i][3]);
        *(float4*)(out + (size_t)r * DMODEL + c0) = v4;
    }
}

// ---------------- launch ---------------------------------------------------------
extern "C" void kernel_launch(void* const* d_in, const int* in_sizes, int n_in,
                              void* d_out, int out_size)
{
    const float* x   = (const float*)d_in[0];
    const int*   pos = (const int*)  d_in[1];
    const float* wq  = (const float*)d_in[2];
    const float* wk  = (const float*)d_in[3];
    const float* wv  = (const float*)d_in[4];
    const float* wo  = (const float*)d_in[5];
    float* out = (float*)d_out;

    rope_table_kernel<<<(S_LEN * (DK / 2) + 255) / 256, 256>>>();

    dim3 g1(DMODEL / 64, MROWS / 64, 3);
    gemm_qkv_kernel<<<g1, 256>>>(x, wq, wk, wv, pos);

    attn_kernel<<<dim3(S_LEN / 64, BATCH * NHEAD), 64>>>();

    gemm_out_kernel<<<dim3(DMODEL / 64, MROWS / 64), 256>>>(wo, out);
}

// round 3
// speedup vs baseline: 1.4882x; 1.4882x over previous
#include <cuda_runtime.h>
#include <cuda_bf16.h>
#include <math.h>
#include <stdint.h>

#define BATCH   2
#define S_LEN   2048
#define NHEAD   16
#define DK      64
#define DMODEL  1024
#define MROWS   (BATCH * S_LEN)   // 4096

// ---------------- scratch (device globals: no allocation allowed) ----------------
__device__ __align__(16) float g_q[BATCH * NHEAD * S_LEN * DK];   // (b,h,s,d)
__device__ __align__(16) float g_k[BATCH * NHEAD * S_LEN * DK];
__device__ __align__(16) float g_v[BATCH * NHEAD * S_LEN * DK];
__device__ __align__(16) float g_att[MROWS * DMODEL];             // (b*s, h*dk)
__device__ float g_cos[S_LEN * (DK / 2)];
__device__ float g_sin[S_LEN * (DK / 2)];

// bf16 split operands
__device__ __align__(16) __nv_bfloat16 g_xh[MROWS * DMODEL];
__device__ __align__(16) __nv_bfloat16 g_xl[MROWS * DMODEL];
__device__ __align__(16) __nv_bfloat16 g_wh[4 * 1024 * DMODEL];   // rows: wq|wk|wv|wo
__device__ __align__(16) __nv_bfloat16 g_wl[4 * 1024 * DMODEL];
__device__ __align__(16) __nv_bfloat16 g_ah[MROWS * DMODEL];
__device__ __align__(16) __nv_bfloat16 g_al[MROWS * DMODEL];

// ---------------- PTX helpers (sm_103-portable: mma.sync / ldmatrix / cp.async) ---
__device__ __forceinline__ uint32_t smem_to_u32(const void* p) {
    uint32_t a;
    asm("{ .reg .u64 t; cvta.to.shared.u64 t, %1; cvt.u32.u64 %0, t; }" : "=r"(a) : "l"(p));
    return a;
}
__device__ __forceinline__ void cp16(uint32_t s, const void* g) {
    asm volatile("cp.async.cg.shared.global [%0], [%1], 16;" :: "r"(s), "l"(g) : "memory");
}
__device__ __forceinline__ void cp_commit() {
    asm volatile("cp.async.commit_group;" ::: "memory");
}
__device__ __forceinline__ void ldmatrix_x4(uint32_t* r, uint32_t addr) {
    asm volatile("ldmatrix.sync.aligned.m8n8.x4.shared.b16 {%0,%1,%2,%3}, [%4];"
        : "=r"(r[0]), "=r"(r[1]), "=r"(r[2]), "=r"(r[3]) : "r"(addr));
}
__device__ __forceinline__ void mma_bf16(float* c, const uint32_t* a, uint32_t b0, uint32_t b1) {
    asm volatile(
        "mma.sync.aligned.m16n8k16.row.col.f32.bf16.bf16.f32 "
        "{%0,%1,%2,%3}, {%4,%5,%6,%7}, {%8,%9}, {%0,%1,%2,%3};"
        : "+f"(c[0]), "+f"(c[1]), "+f"(c[2]), "+f"(c[3])
        : "r"(a[0]), "r"(a[1]), "r"(a[2]), "r"(a[3]), "r"(b0), "r"(b1));
}
__device__ __forceinline__ uint32_t sw128(uint32_t off) {
    return off ^ ((off >> 3) & 0x70);
}

// ---------------- RoPE tables -----------------------------------------------------
__global__ void rope_table_kernel() {
    int idx = blockIdx.x * blockDim.x + threadIdx.x;
    if (idx >= S_LEN * (DK / 2)) return;
    int pos = idx >> 5;
    int pr  = idx & 31;
    double inv = exp(-(double)pr * 0.28782313662425575);
    double ang = (double)pos * inv;
    g_cos[idx] = (float)cos(ang);
    g_sin[idx] = (float)sin(ang);
}

// ---------------- fp32 -> bf16 hi/lo split converters ------------------------------
__device__ __forceinline__ void bf16_split(float v, __nv_bfloat16& h, __nv_bfloat16& l) {
    h = __float2bfloat16_rn(v);
    l = __float2bfloat16_rn(v - __bfloat162float(h));
}
__global__ void convert_x_kernel(const float* __restrict__ x) {
    int i = blockIdx.x * blockDim.x + threadIdx.x;
    __nv_bfloat16 h, l;
    bf16_split(x[i], h, l);
    g_xh[i] = h; g_xl[i] = l;
}
__global__ void convert_w_kernel(const float* __restrict__ wq, const float* __restrict__ wk,
                                 const float* __restrict__ wv, const float* __restrict__ wo) {
    int i = blockIdx.x * blockDim.x + threadIdx.x;
    int n = i >> 10;
    const float* src = (n < 1024) ? wq : (n < 2048) ? wk : (n < 3072) ? wv : wo;
    float v = src[((size_t)(n & 1023) << 10) | (i & 1023)];
    __nv_bfloat16 h, l;
    bf16_split(v, h, l);
    g_wh[i] = h; g_wl[i] = l;
}
__global__ void convert_att_kernel() {
    int i = blockIdx.x * blockDim.x + threadIdx.x;
    __nv_bfloat16 h, l;
    bf16_split(g_att[i], h, l);
    g_ah[i] = h; g_al[i] = l;
}

// ---------------- mma.sync split-bf16 GEMM -----------------------------------------
// D[128x128] fp32 = sum_k A[m,k]*B[n,k]  via Ah*Bh + Ah*Bl + Al*Bh
// MODE 0: A = x split, B = [wq|wk|wv] rows, epilogue RoPE+scatter to g_q/g_k/g_v
// MODE 1: A = att split, B = wo rows (offset 3072), epilogue -> outp
// smem stage: [Ah 16K][Al 16K][Bh 16K][Bl 16K] = 64K, double buffered = 128K
#define GEMM_SMEM_BYTES (2 * 65536)

template <int MODE>
__global__ void __launch_bounds__(256, 1)
gemm_mma(float* __restrict__ outp, const int* __restrict__ positions) {
    extern __shared__ __align__(128) char smem[];
    const uint32_t sb = smem_to_u32(smem);
    const int tid = threadIdx.x;
    const int lane = tid & 31, wid = tid >> 5;
    const int warp_m = wid & 3;        // 4 warps over M (32 rows each)
    const int warp_n = wid >> 2;       // 2 warps over N (64 cols each)

    const int m0 = blockIdx.y << 7;
    const int n0 = blockIdx.x << 7;

    const __nv_bfloat16 *aH, *aL, *bH, *bL;
    if (MODE == 0) {
        aH = g_xh + (size_t)m0 * DMODEL;  aL = g_xl + (size_t)m0 * DMODEL;
        bH = g_wh + (size_t)n0 * DMODEL;  bL = g_wl + (size_t)n0 * DMODEL;
    } else {
        aH = g_ah + (size_t)m0 * DMODEL;  aL = g_al + (size_t)m0 * DMODEL;
        bH = g_wh + (size_t)(3072 + n0) * DMODEL;
        bL = g_wl + (size_t)(3072 + n0) * DMODEL;
    }

    // ---- stage loader: k-chunk kc (64 wide) into buffer stg ----
    auto load_stage = [&](int kc, int stg) {
        const uint32_t sbase = sb + (uint32_t)stg * 65536u;
        #pragma unroll
        for (int i = 0; i < 4; i++) {
            int chunk = tid + (i << 8);          // 0..1023
            int row = chunk >> 3, kseg = chunk & 7;
            size_t g = (size_t)row * DMODEL + (kc << 6) + (kseg << 3);
            uint32_t sw = sw128((uint32_t)((row << 7) + (kseg << 4)));
            cp16(sbase +          sw, aH + g);
            cp16(sbase + 16384u + sw, aL + g);
            cp16(sbase + 32768u + sw, bH + g);
            cp16(sbase + 49152u + sw, bL + g);
        }
        cp_commit();
    };

    load_stage(0, 0);
    load_stage(1, 1);

    float acc[2][8][4];
    #pragma unroll
    for (int a = 0; a < 2; a++)
        #pragma unroll
        for (int b = 0; b < 8; b++)
            #pragma unroll
            for (int c = 0; c < 4; c++) acc[a][b][c] = 0.f;

    for (int kc = 0; kc < 16; kc++) {
        if (kc < 15) asm volatile("cp.async.wait_group 1;" ::: "memory");
        else         asm volatile("cp.async.wait_group 0;" ::: "memory");
        __syncthreads();

        const uint32_t sbase = sb + (uint32_t)(kc & 1) * 65536u;
        #pragma unroll
        for (int ks = 0; ks < 4; ks++) {
            // A fragments (2 m-tiles x hi/lo)
            uint32_t ah[2][4], al[2][4];
            #pragma unroll
            for (int mt = 0; mt < 2; mt++) {
                int m = warp_m * 32 + mt * 16 + ((lane >> 3) & 1) * 8 + (lane & 7);
                int k = ks * 16 + (lane >> 4) * 8;
                uint32_t sw = sw128((uint32_t)(m * 128 + k * 2));
                ldmatrix_x4(ah[mt], sbase + sw);
                ldmatrix_x4(al[mt], sbase + 16384u + sw);
            }
            // B fragments (4 n16-tiles x hi/lo)
            uint32_t bh[4][4], bl[4][4];
            #pragma unroll
            for (int nt = 0; nt < 4; nt++) {
                int n = warp_n * 64 + nt * 16 + (lane >> 4) * 8 + (lane & 7);
                int k = ks * 16 + ((lane >> 3) & 1) * 8;
                uint32_t sw = sw128((uint32_t)(n * 128 + k * 2));
                ldmatrix_x4(bh[nt], sbase + 32768u + sw);
                ldmatrix_x4(bl[nt], sbase + 49152u + sw);
            }
            // MMAs: 3 products
            #pragma unroll
            for (int mt = 0; mt < 2; mt++) {
                #pragma unroll
                for (int nt8 = 0; nt8 < 8; nt8++) {
                    uint32_t b0h = bh[nt8 >> 1][(nt8 & 1) * 2];
                    uint32_t b1h = bh[nt8 >> 1][(nt8 & 1) * 2 + 1];
                    uint32_t b0l = bl[nt8 >> 1][(nt8 & 1) * 2];
                    uint32_t b1l = bl[nt8 >> 1][(nt8 & 1) * 2 + 1];
                    mma_bf16(acc[mt][nt8], ah[mt], b0h, b1h);
                    mma_bf16(acc[mt][nt8], ah[mt], b0l, b1l);
                    mma_bf16(acc[mt][nt8], al[mt], b0h, b1h);
                }
            }
        }
        __syncthreads();
        if (kc + 2 < 16) load_stage(kc + 2, kc & 1);
    }

    // -------- epilogue --------
    const int row0 = lane >> 2;
    const int col0 = (lane & 3) * 2;

    if (MODE == 0) {
        const int z = n0 >> 10;                 // 0=Q 1=K 2=V
        float* zbase = (z == 0) ? g_q : (z == 1) ? g_k : g_v;
        #pragma unroll
        for (int mt = 0; mt < 2; mt++) {
            #pragma unroll
            for (int half = 0; half < 2; half++) {
                int m = m0 + warp_m * 32 + mt * 16 + row0 + half * 8;
                int bidx = m >> 11, s = m & 2047;
                int p = positions[s];
                #pragma unroll
                for (int nt8 = 0; nt8 < 8; nt8++) {
                    int n = n0 + warp_n * 64 + nt8 * 8 + col0;
                    float c0 = acc[mt][nt8][half * 2 + 0];
                    float c1 = acc[mt][nt8][half * 2 + 1];
                    int h = (n & 1023) >> 6, d = n & 63;
                    float* dst = zbase + (((size_t)(bidx * NHEAD + h) * S_LEN + s) * DK + d);
                    if (z < 2) {
                        int pr = d >> 1;
                        float cs = g_cos[p * 32 + pr], sn = g_sin[p * 32 + pr];
                        float2 y = make_float2(c0 * cs - c1 * sn, c0 * sn + c1 * cs);
                        *(float2*)dst = y;
                    } else {
                        *(float2*)dst = make_float2(c0, c1);
                    }
                }
            }
        }
    } else {
        #pragma unroll
        for (int mt = 0; mt < 2; mt++) {
            #pragma unroll
            for (int half = 0; half < 2; half++) {
                int m = m0 + warp_m * 32 + mt * 16 + row0 + half * 8;
                float* dst = outp + (size_t)m * DMODEL + n0 + warp_n * 64 + col0;
                #pragma unroll
                for (int nt8 = 0; nt8 < 8; nt8++) {
                    *(float2*)(dst + nt8 * 8) = make_float2(
                        acc[mt][nt8][half * 2 + 0], acc[mt][nt8][half * 2 + 1]);
                }
            }
        }
    }
}

// ---------------- causal flash attention (unchanged, proven) ----------------------
__global__ __launch_bounds__(64) void attn_kernel() {
    __shared__ __align__(16) float ksh[64 * 64];
    __shared__ __align__(16) float vsh[64 * 64];
    __shared__ float ssh[64 * 33];

    const int tid = threadIdx.x;
    const int qt  = blockIdx.x;
    const int bh  = blockIdx.y;
    const int qi  = qt * 64 + tid;

    const float4* Qp = (const float4*)(g_q + ((size_t)bh * S_LEN + qi) * DK);
    float4 q4[16], o4[16];
    #pragma unroll
    for (int i = 0; i < 16; i++) { q4[i] = Qp[i]; o4[i] = make_float4(0.f, 0.f, 0.f, 0.f); }

    float mrun = -1e30f, l = 0.f;

    for (int kt = 0; kt <= qt; kt++) {
        const float4* kb = (const float4*)(g_k + ((size_t)bh * S_LEN + kt * 64) * DK);
        const float4* vb = (const float4*)(g_v + ((size_t)bh * S_LEN + kt * 64) * DK);
        __syncthreads();
        #pragma unroll
        for (int i = 0; i < 16; i++) {
            int f = tid + i * 64;
            ((float4*)ksh)[f] = kb[f];
            ((float4*)vsh)[f] = vb[f];
        }
        __syncthreads();
        const bool diag = (kt == qt);

        #pragma unroll 1
        for (int half = 0; half < 2; half++) {
            const int jbase = half * 32;
            float mt = -1e30f;
            #pragma unroll 1
            for (int jj = 0; jj < 32; jj++) {
                int j = jbase + jj;
                const float4* kr = (const float4*)(ksh + j * 64);
                float4 a = make_float4(0.f, 0.f, 0.f, 0.f);
                #pragma unroll
                for (int i = 0; i < 16; i++) {
                    float4 k4 = kr[i];
                    a.x += q4[i].x * k4.x; a.y += q4[i].y * k4.y;
                    a.z += q4[i].z * k4.z; a.w += q4[i].w * k4.w;
                }
                float s = (a.x + a.y + a.z + a.w) * 0.125f;
                if (diag && j > tid) s = -1e30f;
                ssh[tid * 33 + jj] = s;
                mt = fmaxf(mt, s);
            }
            float mnew = fmaxf(mrun, mt);
            float corr = __expf(mrun - mnew);
            l *= corr;
            #pragma unroll
            for (int i = 0; i < 16; i++) {
                o4[i].x *= corr; o4[i].y *= corr; o4[i].z *= corr; o4[i].w *= corr;
            }
            #pragma unroll 1
            for (int jj = 0; jj < 32; jj++) {
                float p = __expf(ssh[tid * 33 + jj] - mnew);
                l += p;
                const float4* vr = (const float4*)(vsh + (jbase + jj) * 64);
                #pragma unroll
                for (int i = 0; i < 16; i++) {
                    float4 v4 = vr[i];
                    o4[i].x += p * v4.x; o4[i].y += p * v4.y;
                    o4[i].z += p * v4.z; o4[i].w += p * v4.w;
                }
            }
            mrun = mnew;
        }
    }

    const float inv = 1.f / l;
    const int b = bh / NHEAD, h = bh % NHEAD;
    float4* out = (float4*)(g_att + (size_t)(b * S_LEN + qi) * DMODEL + h * DK);
    #pragma unroll
    for (int i = 0; i < 16; i++) {
        float4 v = o4[i];
        v.x *= inv; v.y *= inv; v.z *= inv; v.w *= inv;
        out[i] = v;
    }
}

// ---------------- launch ----------------------------------------------------------
extern "C" void kernel_launch(void* const* d_in, const int* in_sizes, int n_in,
                              void* d_out, int out_size)
{
    const float* x   = (const float*)d_in[0];
    const int*   pos = (const int*)  d_in[1];
    const float* wq  = (const float*)d_in[2];
    const float* wk  = (const float*)d_in[3];
    const float* wv  = (const float*)d_in[4];
    const float* wo  = (const float*)d_in[5];
    float* out = (float*)d_out;

    cudaFuncSetAttribute(gemm_mma<0>, cudaFuncAttributeMaxDynamicSharedMemorySize, GEMM_SMEM_BYTES);
    cudaFuncSetAttribute(gemm_mma<1>, cudaFuncAttributeMaxDynamicSharedMemorySize, GEMM_SMEM_BYTES);

    rope_table_kernel<<<(S_LEN * (DK / 2) + 255) / 256, 256>>>();
    convert_x_kernel<<<MROWS * DMODEL / 256, 256>>>(x);
    convert_w_kernel<<<4 * 1024 * DMODEL / 256, 256>>>(wq, wk, wv, wo);

    gemm_mma<0><<<dim3(3 * DMODEL / 128, MROWS / 128), 256, GEMM_SMEM_BYTES>>>(nullptr, pos);

    attn_kernel<<<dim3(S_LEN / 64, BATCH * NHEAD), 64>>>();

    convert_att_kernel<<<MROWS * DMODEL / 256, 256>>>();

    gemm_mma<1><<<dim3(DMODEL / 128, MROWS / 128), 256, GEMM_SMEM_BYTES>>>(out, pos);
}

// round 6
// speedup vs baseline: 3.5497x; 2.3852x over previous
#include <cuda_runtime.h>
#include <cuda_bf16.h>
#include <math.h>
#include <stdint.h>

#define BATCH   2
#define S_LEN   2048
#define NHEAD   16
#define DK      64
#define DMODEL  1024
#define MROWS   (BATCH * S_LEN)   // 4096
#define BH      (BATCH * NHEAD)   // 32

// ---------------- scratch (device globals: no allocation allowed) ----------------
__device__ float g_cos[S_LEN * (DK / 2)];
__device__ float g_sin[S_LEN * (DK / 2)];

// bf16 split operands
__device__ __align__(16) __nv_bfloat16 g_xh[MROWS * DMODEL];
__device__ __align__(16) __nv_bfloat16 g_xl[MROWS * DMODEL];
__device__ __align__(16) __nv_bfloat16 g_wh[4 * 1024 * DMODEL];   // rows: wq|wk|wv|wo
__device__ __align__(16) __nv_bfloat16 g_wl[4 * 1024 * DMODEL];
// post-RoPE split Q/K: [bh][s][d];  split V transposed: [bh][d][s]
__device__ __align__(16) __nv_bfloat16 g_qh[BH * S_LEN * DK];
__device__ __align__(16) __nv_bfloat16 g_ql[BH * S_LEN * DK];
__device__ __align__(16) __nv_bfloat16 g_kh[BH * S_LEN * DK];
__device__ __align__(16) __nv_bfloat16 g_kl[BH * S_LEN * DK];
__device__ __align__(16) __nv_bfloat16 g_vth[BH * DK * S_LEN];
__device__ __align__(16) __nv_bfloat16 g_vtl[BH * DK * S_LEN];
// attention output split: [b*s][h*dk]
__device__ __align__(16) __nv_bfloat16 g_ah[MROWS * DMODEL];
__device__ __align__(16) __nv_bfloat16 g_al[MROWS * DMODEL];

// ---------------- PTX helpers (sm_103-portable) ------------------------------------
__device__ __forceinline__ uint32_t smem_to_u32(const void* p) {
    uint32_t a;
    asm("{ .reg .u64 t; cvta.to.shared.u64 t, %1; cvt.u32.u64 %0, t; }" : "=r"(a) : "l"(p));
    return a;
}
__device__ __forceinline__ void cp16(uint32_t s, const void* g) {
    asm volatile("cp.async.cg.shared.global [%0], [%1], 16;" :: "r"(s), "l"(g) : "memory");
}
__device__ __forceinline__ void cp_commit() {
    asm volatile("cp.async.commit_group;" ::: "memory");
}
__device__ __forceinline__ void ldmatrix_x4(uint32_t* r, uint32_t addr) {
    asm volatile("ldmatrix.sync.aligned.m8n8.x4.shared.b16 {%0,%1,%2,%3}, [%4];"
        : "=r"(r[0]), "=r"(r[1]), "=r"(r[2]), "=r"(r[3]) : "r"(addr));
}
__device__ __forceinline__ void mma_bf16(float* c, const uint32_t* a, uint32_t b0, uint32_t b1) {
    asm volatile(
        "mma.sync.aligned.m16n8k16.row.col.f32.bf16.bf16.f32 "
        "{%0,%1,%2,%3}, {%4,%5,%6,%7}, {%8,%9}, {%0,%1,%2,%3};"
        : "+f"(c[0]), "+f"(c[1]), "+f"(c[2]), "+f"(c[3])
        : "r"(a[0]), "r"(a[1]), "r"(a[2]), "r"(a[3]), "r"(b0), "r"(b1));
}
__device__ __forceinline__ uint32_t sw128(uint32_t off) {
    return off ^ ((off >> 3) & 0x70);
}
__device__ __forceinline__ void bf16_split(float v, __nv_bfloat16& h, __nv_bfloat16& l) {
    h = __float2bfloat16_rn(v);
    l = __float2bfloat16_rn(v - __bfloat162float(h));
}
// pack two floats into bf16x2 hi reg + bf16x2 lo reg
__device__ __forceinline__ void pack_split2(float p0, float p1, uint32_t& hi, uint32_t& lo) {
    __nv_bfloat16 h0, l0, h1, l1;
    bf16_split(p0, h0, l0);
    bf16_split(p1, h1, l1);
    __nv_bfloat162 H; H.x = h0; H.y = h1;
    __nv_bfloat162 L; L.x = l0; L.y = l1;
    hi = *(uint32_t*)&H;
    lo = *(uint32_t*)&L;
}
__device__ __forceinline__ void store_split2(__nv_bfloat16* ph, __nv_bfloat16* pl,
                                             float v0, float v1) {
    __nv_bfloat16 h0, l0, h1, l1;
    bf16_split(v0, h0, l0);
    bf16_split(v1, h1, l1);
    __nv_bfloat162 H; H.x = h0; H.y = h1;
    __nv_bfloat162 L; L.x = l0; L.y = l1;
    *(__nv_bfloat162*)ph = H;
    *(__nv_bfloat162*)pl = L;
}

// ---------------- RoPE tables -----------------------------------------------------
__global__ void rope_table_kernel() {
    int idx = blockIdx.x * blockDim.x + threadIdx.x;
    if (idx >= S_LEN * (DK / 2)) return;
    int pos = idx >> 5;
    int pr  = idx & 31;
    double inv = exp(-(double)pr * 0.28782313662425575);
    double ang = (double)pos * inv;
    g_cos[idx] = (float)cos(ang);
    g_sin[idx] = (float)sin(ang);
}

// ---------------- fp32 -> bf16 hi/lo split converters ------------------------------
__global__ void convert_x_kernel(const float* __restrict__ x) {
    int i = blockIdx.x * blockDim.x + threadIdx.x;
    __nv_bfloat16 h, l;
    bf16_split(x[i], h, l);
    g_xh[i] = h; g_xl[i] = l;
}
__global__ void convert_w_kernel(const float* __restrict__ wq, const float* __restrict__ wk,
                                 const float* __restrict__ wv, const float* __restrict__ wo) {
    int i = blockIdx.x * blockDim.x + threadIdx.x;
    int n = i >> 10;
    const float* src = (n < 1024) ? wq : (n < 2048) ? wk : (n < 3072) ? wv : wo;
    float v = src[((size_t)(n & 1023) << 10) | (i & 1023)];
    __nv_bfloat16 h, l;
    bf16_split(v, h, l);
    g_wh[i] = h; g_wl[i] = l;
}

// ---------------- mma.sync split-bf16 GEMM -----------------------------------------
// MODE 0: A = x split, B = [wq|wk|wv]; epilogue RoPE + split-scatter to q/k, transposed v
// MODE 1: A = attention-out split, B = wo (offset 3072); epilogue -> outp (fp32)
#define GEMM_SMEM_BYTES (2 * 65536)

template <int MODE>
__global__ void __launch_bounds__(256, 1)
gemm_mma(float* __restrict__ outp, const int* __restrict__ positions) {
    extern __shared__ __align__(128) char smem[];
    const uint32_t sb = smem_to_u32(smem);
    const int tid = threadIdx.x;
    const int lane = tid & 31, wid = tid >> 5;
    const int warp_m = wid & 3;
    const int warp_n = wid >> 2;

    const int m0 = blockIdx.y << 7;
    const int n0 = blockIdx.x << 7;

    const __nv_bfloat16 *aH, *aL, *bHp, *bLp;
    if (MODE == 0) {
        aH = g_xh + (size_t)m0 * DMODEL;  aL = g_xl + (size_t)m0 * DMODEL;
        bHp = g_wh + (size_t)n0 * DMODEL; bLp = g_wl + (size_t)n0 * DMODEL;
    } else {
        aH = g_ah + (size_t)m0 * DMODEL;  aL = g_al + (size_t)m0 * DMODEL;
        bHp = g_wh + (size_t)(3072 + n0) * DMODEL;
        bLp = g_wl + (size_t)(3072 + n0) * DMODEL;
    }

    auto load_stage = [&](int kc, int stg) {
        const uint32_t sbase = sb + (uint32_t)stg * 65536u;
        #pragma unroll
        for (int i = 0; i < 4; i++) {
            int chunk = tid + (i << 8);
            int row = chunk >> 3, kseg = chunk & 7;
            size_t g = (size_t)row * DMODEL + (kc << 6) + (kseg << 3);
            uint32_t sw = sw128((uint32_t)((row << 7) + (kseg << 4)));
            cp16(sbase +          sw, aH + g);
            cp16(sbase + 16384u + sw, aL + g);
            cp16(sbase + 32768u + sw, bHp + g);
            cp16(sbase + 49152u + sw, bLp + g);
        }
        cp_commit();
    };

    load_stage(0, 0);
    load_stage(1, 1);

    float acc[2][8][4];
    #pragma unroll
    for (int a = 0; a < 2; a++)
        #pragma unroll
        for (int b = 0; b < 8; b++)
            #pragma unroll
            for (int c = 0; c < 4; c++) acc[a][b][c] = 0.f;

    for (int kc = 0; kc < 16; kc++) {
        if (kc < 15) asm volatile("cp.async.wait_group 1;" ::: "memory");
        else         asm volatile("cp.async.wait_group 0;" ::: "memory");
        __syncthreads();

        const uint32_t sbase = sb + (uint32_t)(kc & 1) * 65536u;
        #pragma unroll
        for (int ks = 0; ks < 4; ks++) {
            uint32_t ah[2][4], al[2][4];
            #pragma unroll
            for (int mt = 0; mt < 2; mt++) {
                int m = warp_m * 32 + mt * 16 + ((lane >> 3) & 1) * 8 + (lane & 7);
                int k = ks * 16 + (lane >> 4) * 8;
                uint32_t sw = sw128((uint32_t)(m * 128 + k * 2));
                ldmatrix_x4(ah[mt], sbase + sw);
                ldmatrix_x4(al[mt], sbase + 16384u + sw);
            }
            uint32_t bh[4][4], bl[4][4];
            #pragma unroll
            for (int nt = 0; nt < 4; nt++) {
                int n = warp_n * 64 + nt * 16 + (lane >> 4) * 8 + (lane & 7);
                int k = ks * 16 + ((lane >> 3) & 1) * 8;
                uint32_t sw = sw128((uint32_t)(n * 128 + k * 2));
                ldmatrix_x4(bh[nt], sbase + 32768u + sw);
                ldmatrix_x4(bl[nt], sbase + 49152u + sw);
            }
            #pragma unroll
            for (int mt = 0; mt < 2; mt++) {
                #pragma unroll
                for (int nt8 = 0; nt8 < 8; nt8++) {
                    uint32_t b0h = bh[nt8 >> 1][(nt8 & 1) * 2];
                    uint32_t b1h = bh[nt8 >> 1][(nt8 & 1) * 2 + 1];
                    uint32_t b0l = bl[nt8 >> 1][(nt8 & 1) * 2];
                    uint32_t b1l = bl[nt8 >> 1][(nt8 & 1) * 2 + 1];
                    mma_bf16(acc[mt][nt8], ah[mt], b0h, b1h);
                    mma_bf16(acc[mt][nt8], ah[mt], b0l, b1l);
                    mma_bf16(acc[mt][nt8], al[mt], b0h, b1h);
                }
            }
        }
        __syncthreads();
        if (kc + 2 < 16) load_stage(kc + 2, kc & 1);
    }

    // -------- epilogue --------
    const int row0 = lane >> 2;
    const int col0 = (lane & 3) * 2;

    if (MODE == 0) {
        const int z = n0 >> 10;                 // 0=Q 1=K 2=V
        #pragma unroll
        for (int mt = 0; mt < 2; mt++) {
            #pragma unroll
            for (int half = 0; half < 2; half++) {
                int m = m0 + warp_m * 32 + mt * 16 + row0 + half * 8;
                int bidx = m >> 11, s = m & 2047;
                int p = positions[s];
                #pragma unroll
                for (int nt8 = 0; nt8 < 8; nt8++) {
                    int n = n0 + warp_n * 64 + nt8 * 8 + col0;
                    float c0 = acc[mt][nt8][half * 2 + 0];
                    float c1 = acc[mt][nt8][half * 2 + 1];
                    int h = (n & 1023) >> 6, d = n & 63;
                    int bh_ = bidx * NHEAD + h;
                    if (z < 2) {
                        int pr = d >> 1;
                        float cs = g_cos[p * 32 + pr], sn = g_sin[p * 32 + pr];
                        float y0 = c0 * cs - c1 * sn;
                        float y1 = c0 * sn + c1 * cs;
                        size_t off = ((size_t)bh_ * S_LEN + s) * DK + d;
                        if (z == 0) store_split2(g_qh + off, g_ql + off, y0, y1);
                        else        store_split2(g_kh + off, g_kl + off, y0, y1);
                    } else {
                        __nv_bfloat16 h0, l0, h1, l1;
                        bf16_split(c0, h0, l0);
                        bf16_split(c1, h1, l1);
                        size_t o0 = ((size_t)bh_ * DK + d) * S_LEN + s;
                        size_t o1 = ((size_t)bh_ * DK + d + 1) * S_LEN + s;
                        g_vth[o0] = h0; g_vtl[o0] = l0;
                        g_vth[o1] = h1; g_vtl[o1] = l1;
                    }
                }
            }
        }
    } else {
        #pragma unroll
        for (int mt = 0; mt < 2; mt++) {
            #pragma unroll
            for (int half = 0; half < 2; half++) {
                int m = m0 + warp_m * 32 + mt * 16 + row0 + half * 8;
                float* dst = outp + (size_t)m * DMODEL + n0 + warp_n * 64 + col0;
                #pragma unroll
                for (int nt8 = 0; nt8 < 8; nt8++) {
                    *(float2*)(dst + nt8 * 8) = make_float2(
                        acc[mt][nt8][half * 2 + 0], acc[mt][nt8][half * 2 + 1]);
                }
            }
        }
    }
}

// ---------------- tensor-core causal flash attention --------------------------------
// CTA: 128 q-rows (8 warps x m16), key tiles of 64, double-buffered K/V in smem.
// smem: Qh[16K] Ql[16K], then 2 stages x { Kh 8K, Kl 8K, Vth 8K, Vtl 8K }
#define ATT_SMEM_BYTES (32768 + 2 * 32768)

__global__ void __launch_bounds__(256, 1)
attn_mma() {
    extern __shared__ __align__(128) char smem[];
    const uint32_t sb = smem_to_u32(smem);
    const int tid = threadIdx.x, lane = tid & 31, wid = tid >> 5;
    const int qt = (int)(gridDim.x - 1 - blockIdx.x);   // heavy tiles first
    const int bh = blockIdx.y;
    const int nkt = 2 * (qt + 1);

    const uint32_t sQh = sb, sQl = sb + 16384u;

    // stage Q (split) into smem
    {
        const __nv_bfloat16* qsh = g_qh + ((size_t)bh * S_LEN + qt * 128) * DK;
        const __nv_bfloat16* qsl = g_ql + ((size_t)bh * S_LEN + qt * 128) * DK;
        #pragma unroll
        for (int i = 0; i < 4; i++) {
            int chunk = tid + (i << 8);
            int row = chunk >> 3, seg = chunk & 7;
            size_t g = (size_t)row * DK + (seg << 3);
            uint32_t sw = sw128((uint32_t)((row << 7) + (seg << 4)));
            cp16(sQh + sw, qsh + g);
            cp16(sQl + sw, qsl + g);
        }
    }
    auto kv_load = [&](int kt, int stg) {
        const uint32_t base = sb + 32768u + (uint32_t)stg * 32768u;
        #pragma unroll
        for (int i = 0; i < 2; i++) {
            int chunk = tid + (i << 8);
            int row = chunk >> 3, seg = chunk & 7;
            uint32_t sw = sw128((uint32_t)((row << 7) + (seg << 4)));
            size_t gk = ((size_t)bh * S_LEN + kt * 64 + row) * DK + (seg << 3);
            cp16(base +          sw, g_kh + gk);
            cp16(base +  8192u + sw, g_kl + gk);
            size_t gv = ((size_t)bh * DK + row) * S_LEN + kt * 64 + (seg << 3);
            cp16(base + 16384u + sw, g_vth + gv);
            cp16(base + 24576u + sw, g_vtl + gv);
        }
    };
    kv_load(0, 0);
    cp_commit();          // group: Q + kv0
    kv_load(1, 1);
    cp_commit();          // group: kv1

    uint32_t qfh[4][4], qfl[4][4];
    float m0 = -1e30f, m1 = -1e30f, l0 = 0.f, l1 = 0.f;
    float o[8][4];
    #pragma unroll
    for (int t = 0; t < 8; t++)
        #pragma unroll
        for (int j = 0; j < 4; j++) o[t][j] = 0.f;

    const int r0 = lane >> 2;
    const int c0 = (lane & 3) << 1;

    for (int kt = 0; kt < nkt; kt++) {
        if (kt < nkt - 1) asm volatile("cp.async.wait_group 1;" ::: "memory");
        else              asm volatile("cp.async.wait_group 0;" ::: "memory");
        __syncthreads();

        if (kt == 0) {
            #pragma unroll
            for (int ks = 0; ks < 4; ks++) {
                int m = wid * 16 + ((lane >> 3) & 1) * 8 + (lane & 7);
                int k = ks * 16 + (lane >> 4) * 8;
                uint32_t sw = sw128((uint32_t)(m * 128 + k * 2));
                ldmatrix_x4(qfh[ks], sQh + sw);
                ldmatrix_x4(qfl[ks], sQl + sw);
            }
        }
        const uint32_t base = sb + 32768u + (uint32_t)(kt & 1) * 32768u;

        // ---- S = Q K^T (split, 3 products) ----
        float s[8][4];
        #pragma unroll
        for (int t = 0; t < 8; t++)
            #pragma unroll
            for (int j = 0; j < 4; j++) s[t][j] = 0.f;

        #pragma unroll
        for (int ks = 0; ks < 4; ks++) {
            uint32_t kh[4][4], kl[4][4];
            #pragma unroll
            for (int nt = 0; nt < 4; nt++) {
                int n = nt * 16 + (lane >> 4) * 8 + (lane & 7);
                int k = ks * 16 + ((lane >> 3) & 1) * 8;
                uint32_t sw = sw128((uint32_t)(n * 128 + k * 2));
                ldmatrix_x4(kh[nt], base + sw);
                ldmatrix_x4(kl[nt], base + 8192u + sw);
            }
            #pragma unroll
            for (int t = 0; t < 8; t++) {
                uint32_t b0h = kh[t >> 1][(t & 1) * 2], b1h = kh[t >> 1][(t & 1) * 2 + 1];
                uint32_t b0l = kl[t >> 1][(t & 1) * 2], b1l = kl[t >> 1][(t & 1) * 2 + 1];
                mma_bf16(s[t], qfh[ks], b0h, b1h);
                mma_bf16(s[t], qfh[ks], b0l, b1l);
                mma_bf16(s[t], qfl[ks], b0h, b1h);
            }
        }

        // ---- scale + causal mask ----
        const int qrow0 = qt * 128 + wid * 16 + r0;
        const bool need_mask = (kt >= 2 * qt);
        #pragma unroll
        for (int t = 0; t < 8; t++) {
            #pragma unroll
            for (int j = 0; j < 4; j++) {
                float v = s[t][j] * 0.125f;
                if (need_mask) {
                    int key = kt * 64 + t * 8 + c0 + (j & 1);
                    int qr = qrow0 + ((j >> 1) << 3);
                    if (key > qr) v = -1e30f;
                }
                s[t][j] = v;
            }
        }

        // ---- online softmax ----
        float tm0 = -1e30f, tm1 = -1e30f;
        #pragma unroll
        for (int t = 0; t < 8; t++) {
            tm0 = fmaxf(tm0, fmaxf(s[t][0], s[t][1]));
            tm1 = fmaxf(tm1, fmaxf(s[t][2], s[t][3]));
        }
        tm0 = fmaxf(tm0, __shfl_xor_sync(0xffffffffu, tm0, 1));
        tm0 = fmaxf(tm0, __shfl_xor_sync(0xffffffffu, tm0, 2));
        tm1 = fmaxf(tm1, __shfl_xor_sync(0xffffffffu, tm1, 1));
        tm1 = fmaxf(tm1, __shfl_xor_sync(0xffffffffu, tm1, 2));
        float mn0 = fmaxf(m0, tm0), mn1 = fmaxf(m1, tm1);
        float cr0 = __expf(m0 - mn0), cr1 = __expf(m1 - mn1);
        m0 = mn0; m1 = mn1;

        float rs0 = 0.f, rs1 = 0.f;
        #pragma unroll
        for (int t = 0; t < 8; t++) {
            s[t][0] = __expf(s[t][0] - mn0);
            s[t][1] = __expf(s[t][1] - mn0);
            s[t][2] = __expf(s[t][2] - mn1);
            s[t][3] = __expf(s[t][3] - mn1);
            rs0 += s[t][0] + s[t][1];
            rs1 += s[t][2] + s[t][3];
        }
        rs0 += __shfl_xor_sync(0xffffffffu, rs0, 1);
        rs0 += __shfl_xor_sync(0xffffffffu, rs0, 2);
        rs1 += __shfl_xor_sync(0xffffffffu, rs1, 1);
        rs1 += __shfl_xor_sync(0xffffffffu, rs1, 2);
        l0 = l0 * cr0 + rs0;
        l1 = l1 * cr1 + rs1;
        #pragma unroll
        for (int t = 0; t < 8; t++) {
            o[t][0] *= cr0; o[t][1] *= cr0;
            o[t][2] *= cr1; o[t][3] *= cr1;
        }

        // ---- pack P (split) as A fragments ----
        uint32_t pah[4][4], pal[4][4];
        #pragma unroll
        for (int kc = 0; kc < 4; kc++) {
            pack_split2(s[2 * kc    ][0], s[2 * kc    ][1], pah[kc][0], pal[kc][0]);
            pack_split2(s[2 * kc    ][2], s[2 * kc    ][3], pah[kc][1], pal[kc][1]);
            pack_split2(s[2 * kc + 1][0], s[2 * kc + 1][1], pah[kc][2], pal[kc][2]);
            pack_split2(s[2 * kc + 1][2], s[2 * kc + 1][3], pah[kc][3], pal[kc][3]);
        }

        // ---- O += P V (split, 3 products) ----
        #pragma unroll
        for (int kc = 0; kc < 4; kc++) {
            uint32_t vh[4][4], vl[4][4];
            #pragma unroll
            for (int nt = 0; nt < 4; nt++) {
                int n = nt * 16 + (lane >> 4) * 8 + (lane & 7);
                int k = kc * 16 + ((lane >> 3) & 1) * 8;
                uint32_t sw = sw128((uint32_t)(n * 128 + k * 2));
                ldmatrix_x4(vh[nt], base + 16384u + sw);
                ldmatrix_x4(vl[nt], base + 24576u + sw);
            }
            #pragma unroll
            for (int t = 0; t < 8; t++) {
                uint32_t b0h = vh[t >> 1][(t & 1) * 2], b1h = vh[t >> 1][(t & 1) * 2 + 1];
                uint32_t b0l = vl[t >> 1][(t & 1) * 2], b1l = vl[t >> 1][(t & 1) * 2 + 1];
                mma_bf16(o[t], pah[kc], b0h, b1h);
                mma_bf16(o[t], pah[kc], b0l, b1l);
                mma_bf16(o[t], pal[kc], b0h, b1h);
            }
        }

        __syncthreads();
        if (kt + 2 < nkt) kv_load(kt + 2, kt & 1);
        cp_commit();
    }

    // ---- epilogue: normalize, split to bf16 hi/lo for the W_O GEMM ----
    const float inv0 = 1.f / l0, inv1 = 1.f / l1;
    const int b = bh >> 4, h = bh & 15;
    const size_t mrow0 = (size_t)b * S_LEN + qt * 128 + wid * 16 + r0;
    #pragma unroll
    for (int t = 0; t < 8; t++) {
        int col = h * 64 + t * 8 + c0;
        size_t off0 = mrow0 * DMODEL + col;
        size_t off1 = (mrow0 + 8) * DMODEL + col;
        store_split2(g_ah + off0, g_al + off0, o[t][0] * inv0, o[t][1] * inv0);
        store_split2(g_ah + off1, g_al + off1, o[t][2] * inv1, o[t][3] * inv1);
    }
}

// ---------------- launch ----------------------------------------------------------
extern "C" void kernel_launch(void* const* d_in, const int* in_sizes, int n_in,
                              void* d_out, int out_size)
{
    const float* x   = (const float*)d_in[0];
    const int*   pos = (const int*)  d_in[1];
    const float* wq  = (const float*)d_in[2];
    const float* wk  = (const float*)d_in[3];
    const float* wv  = (const float*)d_in[4];
    const float* wo  = (const float*)d_in[5];
    float* out = (float*)d_out;

    cudaFuncSetAttribute(gemm_mma<0>, cudaFuncAttributeMaxDynamicSharedMemorySize, GEMM_SMEM_BYTES);
    cudaFuncSetAttribute(gemm_mma<1>, cudaFuncAttributeMaxDynamicSharedMemorySize, GEMM_SMEM_BYTES);
    cudaFuncSetAttribute(attn_mma, cudaFuncAttributeMaxDynamicSharedMemorySize, ATT_SMEM_BYTES);

    rope_table_kernel<<<(S_LEN * (DK / 2) + 255) / 256, 256>>>();
    convert_x_kernel<<<MROWS * DMODEL / 256, 256>>>(x);
    convert_w_kernel<<<4 * 1024 * DMODEL / 256, 256>>>(wq, wk, wv, wo);

    gemm_mma<0><<<dim3(3 * DMODEL / 128, MROWS / 128), 256, GEMM_SMEM_BYTES>>>(nullptr, pos);

    attn_mma<<<dim3(S_LEN / 128, BH), 256, ATT_SMEM_BYTES>>>();

    gemm_mma<1><<<dim3(DMODEL / 128, MROWS / 128), 256, GEMM_SMEM_BYTES>>>(out, pos);
}